// round 5
// baseline (speedup 1.0000x reference)
#include <cuda_runtime.h>
#include <cuda_bf16.h>

// Problem constants (Query2Context_15539191677614)
#define T_LEN 16384
#define J_LEN 64
#define D_LEN 1024
#define GRID1 296          // 2 CTAs/SM (148 SMs)
#define QTOT  (T_LEN / 4)  // 4096 row-quads

// Scratch (no cudaMalloc allowed; overwritten every replay -> deterministic)
__device__ float g_partial[GRID1 * D_LEN];  // per-block ctx partials
__device__ float g_bsum[GRID1];             // per-block exp sums
__device__ float g_ctx[D_LEN];              // final normalized context vector

// ---------------------------------------------------------------------------
// Kernel 1: fused rowmax/exp + weighted-sum partials (float4 streaming).
// Block b owns row-quads [q0,q1): rows [4q0, 4q1). Phase A: warp-per-row max
// over J=64 -> e_sh. Phase C: each iter covers 4 rows; thread (g=tid>>8,
// c4=tid&255) loads float4 h[row 4i+g][4*c4..], accumulates with weight
// e_sh[4i+g]; 64B/thread in flight for high MLP. smem reduce across g.
// ---------------------------------------------------------------------------
__global__ __launch_bounds__(1024, 2)
void k_main(const float* __restrict__ h, const float* __restrict__ s) {
    __shared__ float  e_sh[64];        // nrows <= 56
    __shared__ float4 red[4][256];     // 16KB cross-group reduce

    const int b     = blockIdx.x;
    const int q0    = (int)(((long long)b       * QTOT) / GRID1);
    const int q1    = (int)(((long long)(b + 1) * QTOT) / GRID1);
    const int nq    = q1 - q0;         // <= 14
    const int t0    = q0 * 4;
    const int nrows = nq * 4;          // <= 56
    const int tid   = threadIdx.x;
    const int w     = tid >> 5;
    const int lane  = tid & 31;

    // Phase A: warp-per-row max over J=64 (lane reads float2 -> 256B/row)
    for (int r = w; r < nrows; r += 32) {
        const float2 v = __ldcs(reinterpret_cast<const float2*>(
            s + (size_t)(t0 + r) * J_LEN + lane * 2));
        float m = fmaxf(v.x, v.y);
        #pragma unroll
        for (int off = 16; off > 0; off >>= 1)
            m = fmaxf(m, __shfl_xor_sync(0xFFFFFFFFu, m, off));
        if (lane == 0) e_sh[r] = expf(m);
    }
    __syncthreads();

    // Phase B: block exp-sum -> g_bsum[b] (warp 0)
    if (w == 0) {
        float bs = 0.0f;
        for (int r = lane; r < nrows; r += 32) bs += e_sh[r];
        #pragma unroll
        for (int off = 16; off > 0; off >>= 1)
            bs += __shfl_xor_sync(0xFFFFFFFFu, bs, off);
        if (lane == 0) g_bsum[b] = bs;
    }

    // Phase C: float4 stream over h; 4 rows per iteration
    const int g  = tid >> 8;           // row-in-quad 0..3
    const int c4 = tid & 255;          // float4 column 0..255
    float4 acc = make_float4(0.f, 0.f, 0.f, 0.f);
    const float4* __restrict__ hp = reinterpret_cast<const float4*>(
        h + (size_t)(t0 + g) * D_LEN) + c4;
    #pragma unroll 4
    for (int i = 0; i < nq; i++) {
        const float4 v = __ldcs(hp + (size_t)i * D_LEN);   // 4 rows = 4*256 float4
        const float  e = e_sh[4 * i + g];
        acc.x = fmaf(e, v.x, acc.x);
        acc.y = fmaf(e, v.y, acc.y);
        acc.z = fmaf(e, v.z, acc.z);
        acc.w = fmaf(e, v.w, acc.w);
    }
    red[g][c4] = acc;
    __syncthreads();

    // Reduce across the 4 row-groups; thread owns column k = tid
    const int kc4  = tid >> 2;
    const int comp = tid & 3;
    const float* r0 = reinterpret_cast<const float*>(&red[0][kc4]) + comp;
    float val = r0[0] + r0[1024] + r0[2048] + r0[3072];   // float4-stride = 4 floats
    g_partial[b * D_LEN + tid] = val;
}

// ---------------------------------------------------------------------------
// Kernel 2 (tiny): g_ctx[k] = (sum_b partial[b][k]) / (sum_b bsum[b]).
// 32 blocks x 256 thr; warp loads are coalesced over k.
// ---------------------------------------------------------------------------
__global__ __launch_bounds__(256)
void k_ctx() {
    __shared__ float shp[8 * 32];
    __shared__ float shS;

    const int tid   = threadIdx.x;
    const int w     = tid >> 5;
    const int lane  = tid & 31;
    const int kbase = blockIdx.x * 32;

    float acc = 0.0f;
    for (int bb = w; bb < GRID1; bb += 8)
        acc += g_partial[bb * D_LEN + kbase + lane];
    shp[w * 32 + lane] = acc;

    if (w == 1) {            // warp 1 computes S in parallel
        float s = 0.0f;
        for (int bb = lane; bb < GRID1; bb += 32) s += g_bsum[bb];
        #pragma unroll
        for (int off = 16; off > 0; off >>= 1)
            s += __shfl_xor_sync(0xFFFFFFFFu, s, off);
        if (lane == 0) shS = s;
    }
    __syncthreads();

    if (w == 0) {
        float v = 0.0f;
        #pragma unroll
        for (int ww = 0; ww < 8; ww++) v += shp[ww * 32 + lane];
        g_ctx[kbase + lane] = v / shS;
    }
}

// ---------------------------------------------------------------------------
// Kernel 3: pure streaming broadcast. Block k writes out[k, :] (64KB) with
// 16 write-through float4 stores/thread. No smem, no syncs, no prologue.
// ---------------------------------------------------------------------------
__global__ __launch_bounds__(256)
void k_bcast(float4* __restrict__ out) {
    const int k   = blockIdx.x;
    const int tid = threadIdx.x;
    const float v = __ldg(&g_ctx[k]);
    const float4 vv = make_float4(v, v, v, v);
    float4* __restrict__ row = out + (size_t)k * (T_LEN / 4);
    #pragma unroll
    for (int j = 0; j < 16; j++)
        __stwt(row + j * 256 + tid, vv);
}

// ---------------------------------------------------------------------------
extern "C" void kernel_launch(void* const* d_in, const int* in_sizes, int n_in,
                              void* d_out, int out_size) {
    const float* h = (const float*)d_in[0];   // [1, T, d]
    const float* s = (const float*)d_in[1];   // [T, J]
    float* out = (float*)d_out;               // [d, T]

    k_main<<<GRID1, 1024>>>(h, s);
    k_ctx<<<D_LEN / 32, 256>>>();
    k_bcast<<<D_LEN, 256>>>((float4*)out);
}

// round 7
// speedup vs baseline: 1.1985x; 1.1985x over previous
#include <cuda_runtime.h>
#include <cuda_bf16.h>
#include <cstdint>

// Problem constants (Query2Context_15539191677614)
#define T_LEN 16384
#define J_LEN 64
#define D_LEN 1024
#define GRID1 296          // 2 CTAs/SM (148 SMs)
#define QTOT  (T_LEN / 4)  // 4096 row-quads

// Scratch (no cudaMalloc allowed; overwritten every replay -> deterministic)
__device__ float g_partial[GRID1 * D_LEN];  // per-block ctx partials
__device__ float g_bsum[GRID1];             // per-block exp sums

__device__ __forceinline__ uint32_t smem_u32(const void* p) {
    uint32_t a;
    asm("{ .reg .u64 t; cvta.to.shared.u64 t, %1; cvt.u32.u64 %0, t; }"
        : "=r"(a) : "l"(p));
    return a;
}

// ---------------------------------------------------------------------------
// Kernel 1: fused rowmax/exp + weighted-sum partials (float4 streaming).
// Identical to R5's k_main (measured 15.9us).
// ---------------------------------------------------------------------------
__global__ __launch_bounds__(1024, 2)
void k_main(const float* __restrict__ h, const float* __restrict__ s) {
    __shared__ float  e_sh[64];        // nrows <= 56
    __shared__ float4 red[4][256];     // 16KB cross-group reduce

    const int b     = blockIdx.x;
    const int q0    = (int)(((long long)b       * QTOT) / GRID1);
    const int q1    = (int)(((long long)(b + 1) * QTOT) / GRID1);
    const int nq    = q1 - q0;         // <= 14
    const int t0    = q0 * 4;
    const int nrows = nq * 4;          // <= 56
    const int tid   = threadIdx.x;
    const int w     = tid >> 5;
    const int lane  = tid & 31;

    // Phase A: warp-per-row max over J=64 (lane reads float2 -> 256B/row)
    for (int r = w; r < nrows; r += 32) {
        const float2 v = __ldcs(reinterpret_cast<const float2*>(
            s + (size_t)(t0 + r) * J_LEN + lane * 2));
        float m = fmaxf(v.x, v.y);
        #pragma unroll
        for (int off = 16; off > 0; off >>= 1)
            m = fmaxf(m, __shfl_xor_sync(0xFFFFFFFFu, m, off));
        if (lane == 0) e_sh[r] = expf(m);
    }
    __syncthreads();

    // Phase B: block exp-sum -> g_bsum[b] (warp 0)
    if (w == 0) {
        float bs = 0.0f;
        for (int r = lane; r < nrows; r += 32) bs += e_sh[r];
        #pragma unroll
        for (int off = 16; off > 0; off >>= 1)
            bs += __shfl_xor_sync(0xFFFFFFFFu, bs, off);
        if (lane == 0) g_bsum[b] = bs;
    }

    // Phase C: float4 stream over h; 4 rows per iteration
    const int g  = tid >> 8;           // row-in-quad 0..3
    const int c4 = tid & 255;          // float4 column 0..255
    float4 acc = make_float4(0.f, 0.f, 0.f, 0.f);
    const float4* __restrict__ hp = reinterpret_cast<const float4*>(
        h + (size_t)(t0 + g) * D_LEN) + c4;
    #pragma unroll 4
    for (int i = 0; i < nq; i++) {
        const float4 v = __ldcs(hp + (size_t)i * D_LEN);
        const float  e = e_sh[4 * i + g];
        acc.x = fmaf(e, v.x, acc.x);
        acc.y = fmaf(e, v.y, acc.y);
        acc.z = fmaf(e, v.z, acc.z);
        acc.w = fmaf(e, v.w, acc.w);
    }
    red[g][c4] = acc;
    __syncthreads();

    // Reduce across the 4 row-groups; thread owns column k = tid
    const int kc4  = tid >> 2;
    const int comp = tid & 3;
    const float* r0 = reinterpret_cast<const float*>(&red[0][kc4]) + comp;
    g_partial[b * D_LEN + tid] = r0[0] + r0[1024] + r0[2048] + r0[3072];
}

// ---------------------------------------------------------------------------
// Kernel 2: per-k reduce + normalize + broadcast via TMA BULK STORES.
// Block k: gather 296 partials & bsums (L2-hot), tree-reduce, compute
// v = ctx_k / S, fill a 16KB smem tile with v, then issue 4 async
// cp.async.bulk stores (16KB each) covering out[k, 0..T) = 64KB.
// Bulk stores go through the async proxy: full-line writes, no STG
// wavefront replays, no write-allocate.
// ---------------------------------------------------------------------------
__global__ __launch_bounds__(512)
void k_out(float* __restrict__ out) {
    __shared__ float  shp[512];
    __shared__ float  shs[512];
    __shared__ __align__(128) float4 buf[1024];   // 16KB broadcast tile

    const int k   = blockIdx.x;
    const int tid = threadIdx.x;

    shp[tid] = (tid < GRID1) ? g_partial[tid * D_LEN + k] : 0.0f;
    shs[tid] = (tid < GRID1) ? g_bsum[tid]                : 0.0f;
    __syncthreads();

    #pragma unroll
    for (int off = 256; off > 0; off >>= 1) {
        if (tid < off) {
            shp[tid] += shp[tid + off];
            shs[tid] += shs[tid + off];
        }
        __syncthreads();
    }

    const float v = shp[0] / shs[0];
    const float4 vv = make_float4(v, v, v, v);
    buf[tid]       = vv;                 // 512 * 16B
    buf[tid + 512] = vv;                 // + 512 * 16B = 16KB
    __syncthreads();
    asm volatile("fence.proxy.async.shared::cta;" ::: "memory");

    if (tid == 0) {
        const uint32_t src = smem_u32(buf);
        float* row = out + (size_t)k * T_LEN;   // 64KB per row
        #pragma unroll
        for (int c = 0; c < 4; c++) {
            asm volatile(
                "cp.async.bulk.global.shared::cta.bulk_group [%0], [%1], %2;"
                :: "l"(row + c * 4096), "r"(src), "n"(16384)
                : "memory");
        }
        asm volatile("cp.async.bulk.commit_group;" ::: "memory");
        asm volatile("cp.async.bulk.wait_group 0;" ::: "memory");
    }
}

// ---------------------------------------------------------------------------
extern "C" void kernel_launch(void* const* d_in, const int* in_sizes, int n_in,
                              void* d_out, int out_size) {
    const float* h = (const float*)d_in[0];   // [1, T, d]
    const float* s = (const float*)d_in[1];   // [T, J]
    float* out = (float*)d_out;               // [d, T]

    k_main<<<GRID1, 1024>>>(h, s);
    k_out<<<D_LEN, 512>>>(out);
}